// round 6
// baseline (speedup 1.0000x reference)
#include <cuda_runtime.h>
#include <cuda_bf16.h>
#include <math.h>
#include <stdint.h>

// ---------------------------------------------------------------------------
// Problem constants
// ---------------------------------------------------------------------------
#define BB   64
#define SS   32
#define HH   1024
#define RR   256
#define DEPTH 9
#define MAXM (BB*512)

#define SELU_SCALE 1.0507009873554805f
#define SELU_ALPHA 1.6732632423543772f

typedef __nv_bfloat16 bf16;

__device__ __forceinline__ float seluf(float v) {
    return v > 0.f ? SELU_SCALE * v : SELU_SCALE * SELU_ALPHA * expm1f(v);
}
__device__ __forceinline__ float sigmoidf_(float v) {
    return 1.f / (1.f + __expf(-v));
}
__device__ __forceinline__ void split1(float v, bf16& h, bf16& l) {
    h = __float2bfloat16(v);
    l = __float2bfloat16(v - __bfloat162float(h));
}

// ---------------------------------------------------------------------------
// Scratch (device globals; allocation is forbidden)
// ---------------------------------------------------------------------------
__device__ float g_xcA[(size_t)MAXM * HH];
__device__ float g_xcB[(size_t)MAXM * HH];
__device__ float g_hcA[(size_t)MAXM * RR];
__device__ float g_hcB[(size_t)MAXM * RR];
__device__ float g_dA[MAXM];
__device__ float g_dB[MAXM];
__device__ float g_gi[(size_t)MAXM * 3 * RR];
__device__ float g_gh[(size_t)MAXM * 3 * RR];
__device__ float g_y [(size_t)BB * SS * HH];
__device__ bf16 g_sxh[(size_t)BB * SS * HH];
__device__ bf16 g_sxl[(size_t)BB * SS * HH];
__device__ bf16 g_xcAh[(size_t)MAXM * HH];
__device__ bf16 g_xcAl[(size_t)MAXM * HH];
__device__ bf16 g_xcBh[(size_t)MAXM * HH];
__device__ bf16 g_xcBl[(size_t)MAXM * HH];
__device__ bf16 g_hcAh[(size_t)MAXM * RR];
__device__ bf16 g_hcAl[(size_t)MAXM * RR];
__device__ bf16 g_hcBh[(size_t)MAXM * RR];
__device__ bf16 g_hcBl[(size_t)MAXM * RR];
__device__ bf16 g_xhh[(size_t)MAXM * (HH + RR)];
__device__ bf16 g_xhl[(size_t)MAXM * (HH + RR)];
__device__ bf16 g_lrh[(size_t)(MAXM/2) * 2 * HH];
__device__ bf16 g_lrl[(size_t)(MAXM/2) * 2 * HH];
__device__ bf16 g_Whidh[HH * HH];
__device__ bf16 g_Whidl[HH * HH];
__device__ bf16 g_Wbrh[2 * HH * (HH + RR)];
__device__ bf16 g_Wbrl[2 * HH * (HH + RR)];
__device__ bf16 g_Wihh[3 * RR * HH];
__device__ bf16 g_Wihl[3 * RR * HH];
__device__ bf16 g_Whhh[3 * RR * RR];
__device__ bf16 g_Whhl[3 * RR * RR];

// ---------------------------------------------------------------------------
// mma.sync helpers
// ---------------------------------------------------------------------------
__device__ __forceinline__ void ldsm4(uint32_t* r, uint32_t a) {
    asm volatile("ldmatrix.sync.aligned.m8n8.x4.shared.b16 {%0,%1,%2,%3}, [%4];"
        : "=r"(r[0]), "=r"(r[1]), "=r"(r[2]), "=r"(r[3]) : "r"(a));
}
__device__ __forceinline__ void mma_bf16(float* d, const uint32_t* a, uint32_t b0, uint32_t b1) {
    asm volatile("mma.sync.aligned.m16n8k16.row.col.f32.bf16.bf16.f32 "
        "{%0,%1,%2,%3}, {%4,%5,%6,%7}, {%8,%9}, {%0,%1,%2,%3};"
        : "+f"(d[0]), "+f"(d[1]), "+f"(d[2]), "+f"(d[3])
        : "r"(a[0]), "r"(a[1]), "r"(a[2]), "r"(a[3]), "r"(b0), "r"(b1));
}
__device__ __forceinline__ void cpa16(uint32_t dst, const void* src, int srcsize) {
    asm volatile("cp.async.cg.shared.global [%0], [%1], 16, %2;"
                 :: "r"(dst), "l"(src), "r"(srcsize));
}
__device__ __forceinline__ uint32_t smem_u32(const void* p) {
    return (uint32_t)__cvta_generic_to_shared(p);
}

// ---------------------------------------------------------------------------
// HGEMM bf16x3 split, cp.async 3-stage pipeline, BK=64:
//   C[M,N] = epi( Ah@Wh^T + Al@Wh^T + Ah@Wl^T + bias )
//   EPI 0: bias   EPI 1: selu   EPI 2: P[r>>1] - selu
//   OF32 -> fp32 out, OBF -> bf16 hi/lo out
// Requires N % 128 == 0, K % 64 == 0. 128x128 CTA tile, 8 warps of 64x32.
// Stage = A(128x128B) + B(128x128B) = 32 KB; 3 stages = 96 KB dynamic smem.
// ---------------------------------------------------------------------------
#define HG_STAGE 32768
#define HG_DYNSMEM (3 * HG_STAGE)

template<int EPI, bool OF32, bool OBF>
__global__ __launch_bounds__(256, 2)
void hgemm3(const bf16* __restrict__ Ah, const bf16* __restrict__ Al,
            const bf16* __restrict__ Wh, const bf16* __restrict__ Wl,
            const float* __restrict__ bias,
            float* __restrict__ Cf, bf16* __restrict__ Chi, bf16* __restrict__ Clo,
            int M, int N, int K, const float* __restrict__ P)
{
    extern __shared__ char dynsm[];
    const uint32_t smBase = smem_u32(dynsm);

    const int tid = threadIdx.x;
    const int warp = tid >> 5, lane = tid & 31;
    const int wm = warp >> 2, wn = warp & 3;      // 2 x 4 warp grid
    const int row0 = blockIdx.y * 128, col0 = blockIdx.x * 128;

    const int kt = K >> 6;                        // 64-wide k-tiles per phase
    const int T = 3 * kt;

    float acc[4][4][4];
    #pragma unroll
    for (int a = 0; a < 4; a++)
        #pragma unroll
        for (int b = 0; b < 4; b++)
            #pragma unroll
            for (int c = 0; c < 4; c++) acc[a][b][c] = 0.f;

    // ---- async load geometry: thread -> (row, 4 chunks of 16B) ----
    const int lrow = tid >> 1;                    // 0..127
    const int cb0  = (tid & 1) * 4;               // first chunk (of 8 per 128B row)
    const int grA  = row0 + lrow;
    const int okA  = (grA < M) ? 16 : 0;
    const size_t offA = (size_t)((grA < M) ? grA : 0) * K;
    const size_t offW = (size_t)(col0 + lrow) * K;

    auto load_stage = [&](int it, int buf) {
        int ph = (it >= 2 * kt) ? 2 : (it >= kt ? 1 : 0);
        int k0 = (it - ph * kt) << 6;             // bf16 elems
        const bf16* Ap = (ph == 1) ? Al : Ah;
        const bf16* Wp = (ph == 2) ? Wl : Wh;
        uint32_t sA = smBase + buf * HG_STAGE + lrow * 128;
        uint32_t sB = sA + 16384;
        #pragma unroll
        for (int j = 0; j < 4; j++) {
            int chunk = cb0 + j;
            uint32_t sw = (uint32_t)((chunk * 16) ^ ((lrow & 7) * 16));
            cpa16(sA + sw, Ap + offA + k0 + chunk * 8, okA);
            cpa16(sB + sw, Wp + offW + k0 + chunk * 8, 16);
        }
        asm volatile("cp.async.commit_group;" ::: "memory");
    };

    load_stage(0, 0);
    load_stage(1, 1);

    // ---- ldmatrix addressing (within a stage buffer) ----
    const int aRow = wm * 64 + (lane & 15);       // + mt*16
    const int aCsel = (lane >> 4) * 16;           // 16B half within k16
    const int bRow = wn * 32 + (lane & 7) + ((lane >> 4) << 3);  // + p*16
    const int bCsel = ((lane >> 3) & 1) * 16;

    for (int it = 0; it < T; ++it) {
        asm volatile("cp.async.wait_group 1;" ::: "memory");
        __syncthreads();

        if (it + 2 < T) load_stage(it + 2, (it + 2) % 3);

        const uint32_t sb = smBase + (it % 3) * HG_STAGE;
        #pragma unroll
        for (int s = 0; s < 4; s++) {             // four k16 sub-steps
            uint32_t afr[4][4], bfr[2][4];
            #pragma unroll
            for (int mt = 0; mt < 4; mt++) {
                int r = aRow + mt * 16;
                uint32_t col = (uint32_t)((s * 32 + aCsel) ^ ((r & 7) * 16));
                ldsm4(afr[mt], sb + r * 128 + col);
            }
            #pragma unroll
            for (int p = 0; p < 2; p++) {
                int r = bRow + p * 16;
                uint32_t col = (uint32_t)((s * 32 + bCsel) ^ ((r & 7) * 16));
                ldsm4(bfr[p], sb + 16384 + r * 128 + col);
            }
            #pragma unroll
            for (int mt = 0; mt < 4; mt++)
                #pragma unroll
                for (int nt = 0; nt < 4; nt++)
                    mma_bf16(acc[mt][nt], afr[mt],
                             bfr[nt >> 1][(nt & 1) * 2], bfr[nt >> 1][(nt & 1) * 2 + 1]);
        }
    }

    // ---- epilogue ----
    const int g = lane >> 2, t = lane & 3;
    #pragma unroll
    for (int mt = 0; mt < 4; mt++) {
        #pragma unroll
        for (int half = 0; half < 2; half++) {
            int r = row0 + wm * 64 + mt * 16 + g + half * 8;
            if (r >= M) continue;
            #pragma unroll
            for (int nt = 0; nt < 4; nt++) {
                int c = col0 + wn * 32 + nt * 8 + (t << 1);
                float v0 = acc[mt][nt][half * 2 + 0] + bias[c];
                float v1 = acc[mt][nt][half * 2 + 1] + bias[c + 1];
                if (EPI == 1) { v0 = seluf(v0); v1 = seluf(v1); }
                if (EPI == 2) {
                    float2 p = *(const float2*)(P + (size_t)(r >> 1) * HH + c);
                    v0 = p.x - seluf(v0);
                    v1 = p.y - seluf(v1);
                }
                if (OF32) *(float2*)(Cf + (size_t)r * N + c) = make_float2(v0, v1);
                if (OBF) {
                    bf16 h0, l0, h1, l1;
                    split1(v0, h0, l0); split1(v1, h1, l1);
                    *(__nv_bfloat162*)(Chi + (size_t)r * N + c) = __nv_bfloat162(h0, h1);
                    *(__nv_bfloat162*)(Clo + (size_t)r * N + c) = __nv_bfloat162(l0, l1);
                }
            }
        }
    }
}

// ---------------------------------------------------------------------------
// Elementwise kernels
// ---------------------------------------------------------------------------
__global__ void split_kernel(const float* __restrict__ in, bf16* __restrict__ h,
                             bf16* __restrict__ l, int n) {
    int i = blockIdx.x * blockDim.x + threadIdx.x;
    if (i < n) split1(in[i], h[i], l[i]);
}

__global__ void selu_split_kernel(const float* __restrict__ in, bf16* __restrict__ h,
                                  bf16* __restrict__ l, int n) {
    int i = blockIdx.x * blockDim.x + threadIdx.x;
    if (i < n) split1(seluf(in[i]), h[i], l[i]);
}

__global__ void mean_split_kernel(const float* __restrict__ y, float* __restrict__ xc,
                                  bf16* __restrict__ xch, bf16* __restrict__ xcl) {
    int i = blockIdx.x * blockDim.x + threadIdx.x;
    if (i >= BB * HH) return;
    int b = i >> 10, h = i & (HH - 1);
    float s = 0.f;
    #pragma unroll 8
    for (int t = 0; t < SS; t++) s += y[((size_t)(b * SS + t)) * HH + h];
    float v = s * (1.f / SS);
    xc[i] = v;
    split1(v, xch[i], xcl[i]);
}

__global__ void zero32_kernel(uint32_t* p, int n) {
    int i = blockIdx.x * blockDim.x + threadIdx.x;
    if (i < n) p[i] = 0u;
}

__global__ void gru_split_kernel(const float* __restrict__ gi, const float* __restrict__ gh,
                                 float* __restrict__ hc, bf16* __restrict__ hch,
                                 bf16* __restrict__ hcl, int M) {
    int i = blockIdx.x * blockDim.x + threadIdx.x;
    if (i >= M * RR) return;
    int m = i >> 8, j = i & (RR - 1);
    size_t o = (size_t)m * (3 * RR) + j;
    float ir = gi[o], iz = gi[o + RR], inn = gi[o + 2 * RR];
    float hr = gh[o], hz = gh[o + RR], hn  = gh[o + 2 * RR];
    float r = sigmoidf_(ir + hr);
    float z = sigmoidf_(iz + hz);
    float n = tanhf(inn + r * hn);
    size_t ho = (size_t)m * RR + j;
    float v = (1.f - z) * n + z * hc[ho];
    hc[ho] = v;
    split1(v, hch[ho], hcl[ho]);
}

__global__ void concat_bf_kernel(const bf16* __restrict__ xch, const bf16* __restrict__ xcl,
                                 const bf16* __restrict__ hch, const bf16* __restrict__ hcl,
                                 bf16* __restrict__ xhh, bf16* __restrict__ xhl, int M) {
    int i = blockIdx.x * blockDim.x + threadIdx.x;
    if (i >= M * 320) return;
    int m = i / 320, k = i - m * 320;
    uint2 vh, vl;
    if (k < 256) {
        vh = ((const uint2*)xch)[(size_t)m * 256 + k];
        vl = ((const uint2*)xcl)[(size_t)m * 256 + k];
    } else {
        vh = ((const uint2*)hch)[(size_t)m * 64 + (k - 256)];
        vl = ((const uint2*)hcl)[(size_t)m * 64 + (k - 256)];
    }
    ((uint2*)xhh)[(size_t)m * 320 + k] = vh;
    ((uint2*)xhl)[(size_t)m * 320 + k] = vl;
}

__global__ void hb_kernel(const float* __restrict__ xc, const float* __restrict__ hc,
                          const float* __restrict__ Whb, const float* __restrict__ bhb,
                          const float* __restrict__ dIn, float* __restrict__ dOut, int M) {
    int w = (blockIdx.x * blockDim.x + threadIdx.x) >> 5;
    int lane = threadIdx.x & 31;
    if (w >= M) return;
    const float4* xr = (const float4*)(xc + (size_t)w * HH);
    const float4* hr = (const float4*)(hc + (size_t)w * RR);
    const float4* w4 = (const float4*)Whb;
    float s = 0.f;
    #pragma unroll 4
    for (int i = lane; i < 256; i += 32) {
        float4 a = xr[i], b = w4[i];
        s += a.x * b.x + a.y * b.y + a.z * b.z + a.w * b.w;
    }
    #pragma unroll 2
    for (int i = lane; i < 64; i += 32) {
        float4 a = hr[i], b = w4[256 + i];
        s += a.x * b.x + a.y * b.y + a.z * b.z + a.w * b.w;
    }
    #pragma unroll
    for (int o = 16; o; o >>= 1) s += __shfl_xor_sync(0xffffffffu, s, o);
    if (lane == 0) dOut[w] = dIn[w] + sigmoidf_(s + bhb[0]);
}

__global__ void repeat_kernel(const float* __restrict__ hcIn, const bf16* __restrict__ hcInH,
                              const bf16* __restrict__ hcInL, const float* __restrict__ dIn,
                              float* __restrict__ hcOut, bf16* __restrict__ hcOutH,
                              bf16* __restrict__ hcOutL, float* __restrict__ dOut, int M2) {
    int i = blockIdx.x * blockDim.x + threadIdx.x;
    if (i >= M2 * 64) return;
    int m = i >> 6, j = i & 63;
    ((float4*)hcOut)[(size_t)m * 64 + j] = ((const float4*)hcIn)[(size_t)(m >> 1) * 64 + j];
    ((uint2*)hcOutH)[(size_t)m * 64 + j] = ((const uint2*)hcInH)[(size_t)(m >> 1) * 64 + j];
    ((uint2*)hcOutL)[(size_t)m * 64 + j] = ((const uint2*)hcInL)[(size_t)(m >> 1) * 64 + j];
    if (j == 0) dOut[m] = dIn[m >> 1];
}

__global__ void out_kernel(const float* __restrict__ xc, const float* __restrict__ dep,
                           float* __restrict__ out) {
    int i = blockIdx.x * blockDim.x + threadIdx.x;
    if (i >= MAXM * (HH + 1)) return;
    int m = i / (HH + 1), k = i - m * (HH + 1);
    out[i] = (k < HH) ? xc[(size_t)m * HH + k] : dep[m];
}

// ---------------------------------------------------------------------------
// Host driver (graph-capturable: only kernel launches)
// ---------------------------------------------------------------------------
static inline int cdiv(int a, int b) { return (a + b - 1) / b; }

extern "C" void kernel_launch(void* const* d_in, const int* in_sizes, int n_in,
                              void* d_out, int out_size)
{
    const float* x        = (const float*)d_in[0];
    const float* W_hidden = (const float*)d_in[1];
    const float* b_hidden = (const float*)d_in[2];
    const float* W_hb     = (const float*)d_in[3];
    const float* b_hb     = (const float*)d_in[4];
    const float* W_branch = (const float*)d_in[5];
    const float* b_branch = (const float*)d_in[6];
    const float* W_ih     = (const float*)d_in[7];
    const float* W_hh     = (const float*)d_in[8];
    const float* b_ih     = (const float*)d_in[9];
    const float* b_hh     = (const float*)d_in[10];

    cudaFuncSetAttribute(hgemm3<0, true, false>, cudaFuncAttributeMaxDynamicSharedMemorySize, HG_DYNSMEM);
    cudaFuncSetAttribute(hgemm3<1, true, false>, cudaFuncAttributeMaxDynamicSharedMemorySize, HG_DYNSMEM);
    cudaFuncSetAttribute(hgemm3<1, false, true>, cudaFuncAttributeMaxDynamicSharedMemorySize, HG_DYNSMEM);
    cudaFuncSetAttribute(hgemm3<2, true, true>,  cudaFuncAttributeMaxDynamicSharedMemorySize, HG_DYNSMEM);

    float *xcA, *xcB, *hcA, *hcB, *dA, *dB, *gi, *gh, *y;
    bf16 *sxh, *sxl, *xcAh, *xcAl, *xcBh, *xcBl, *hcAh, *hcAl, *hcBh, *hcBl;
    bf16 *xhh, *xhl, *lrh, *lrl;
    bf16 *Whidh, *Whidl, *Wbrh, *Wbrl, *Wihh, *Wihl, *Whhh, *Whhl;

    cudaGetSymbolAddress((void**)&xcA, g_xcA);  cudaGetSymbolAddress((void**)&xcB, g_xcB);
    cudaGetSymbolAddress((void**)&hcA, g_hcA);  cudaGetSymbolAddress((void**)&hcB, g_hcB);
    cudaGetSymbolAddress((void**)&dA,  g_dA);   cudaGetSymbolAddress((void**)&dB,  g_dB);
    cudaGetSymbolAddress((void**)&gi,  g_gi);   cudaGetSymbolAddress((void**)&gh,  g_gh);
    cudaGetSymbolAddress((void**)&y,   g_y);
    cudaGetSymbolAddress((void**)&sxh, g_sxh);  cudaGetSymbolAddress((void**)&sxl, g_sxl);
    cudaGetSymbolAddress((void**)&xcAh, g_xcAh); cudaGetSymbolAddress((void**)&xcAl, g_xcAl);
    cudaGetSymbolAddress((void**)&xcBh, g_xcBh); cudaGetSymbolAddress((void**)&xcBl, g_xcBl);
    cudaGetSymbolAddress((void**)&hcAh, g_hcAh); cudaGetSymbolAddress((void**)&hcAl, g_hcAl);
    cudaGetSymbolAddress((void**)&hcBh, g_hcBh); cudaGetSymbolAddress((void**)&hcBl, g_hcBl);
    cudaGetSymbolAddress((void**)&xhh, g_xhh);  cudaGetSymbolAddress((void**)&xhl, g_xhl);
    cudaGetSymbolAddress((void**)&lrh, g_lrh);  cudaGetSymbolAddress((void**)&lrl, g_lrl);
    cudaGetSymbolAddress((void**)&Whidh, g_Whidh); cudaGetSymbolAddress((void**)&Whidl, g_Whidl);
    cudaGetSymbolAddress((void**)&Wbrh, g_Wbrh);   cudaGetSymbolAddress((void**)&Wbrl, g_Wbrl);
    cudaGetSymbolAddress((void**)&Wihh, g_Wihh);   cudaGetSymbolAddress((void**)&Wihl, g_Wihl);
    cudaGetSymbolAddress((void**)&Whhh, g_Whhh);   cudaGetSymbolAddress((void**)&Whhl, g_Whhl);

    const int nsx = BB * SS * HH;

    // ---- weight splits ----
    split_kernel<<<cdiv(HH*HH, 256), 256>>>(W_hidden, Whidh, Whidl, HH*HH);
    split_kernel<<<cdiv(2*HH*(HH+RR), 256), 256>>>(W_branch, Wbrh, Wbrl, 2*HH*(HH+RR));
    split_kernel<<<cdiv(3*RR*HH, 256), 256>>>(W_ih, Wihh, Wihl, 3*RR*HH);
    split_kernel<<<cdiv(3*RR*RR, 256), 256>>>(W_hh, Whhh, Whhl, 3*RR*RR);

    // ---- root: xc0 = mean_s selu(selu(x) @ W_hidden^T + b_hidden) ----
    selu_split_kernel<<<cdiv(nsx, 256), 256>>>(x, sxh, sxl, nsx);
    hgemm3<1, true, false><<<dim3(HH/128, (BB*SS)/128), 256, HG_DYNSMEM>>>(
        sxh, sxl, Whidh, Whidl, b_hidden, y, nullptr, nullptr, BB*SS, HH, HH, nullptr);
    mean_split_kernel<<<cdiv(BB*HH, 256), 256>>>(y, xcA, xcAh, xcAl);

    zero32_kernel<<<cdiv(BB*RR, 256), 256>>>((uint32_t*)hcA, BB*RR);
    zero32_kernel<<<cdiv(BB*RR/2, 256), 256>>>((uint32_t*)hcAh, BB*RR/2);
    zero32_kernel<<<cdiv(BB*RR/2, 256), 256>>>((uint32_t*)hcAl, BB*RR/2);
    zero32_kernel<<<1, 64>>>((uint32_t*)dA, BB);

    // ---- levels 0 .. DEPTH-1 ----
    for (int d = 0; d < DEPTH; d++) {
        int M  = BB << d;
        int M2 = M << 1;
        int gy = cdiv(M, 128);

        hgemm3<0, true, false><<<dim3(768/128, gy), 256, HG_DYNSMEM>>>(
            xcAh, xcAl, Wihh, Wihl, b_ih, gi, nullptr, nullptr, M, 768, HH, nullptr);
        hgemm3<0, true, false><<<dim3(768/128, gy), 256, HG_DYNSMEM>>>(
            hcAh, hcAl, Whhh, Whhl, b_hh, gh, nullptr, nullptr, M, 768, RR, nullptr);
        gru_split_kernel<<<cdiv(M*RR, 256), 256>>>(gi, gh, hcA, hcAh, hcAl, M);

        hb_kernel<<<cdiv(M*32, 256), 256>>>(xcA, hcA, W_hb, b_hb, dA, dA, M);
        concat_bf_kernel<<<cdiv(M*320, 256), 256>>>(xcAh, xcAl, hcAh, hcAl, xhh, xhl, M);

        hgemm3<1, false, true><<<dim3(2*HH/128, gy), 256, HG_DYNSMEM>>>(
            xhh, xhl, Wbrh, Wbrl, b_branch, nullptr, lrh, lrl, M, 2*HH, HH+RR, nullptr);

        hgemm3<2, true, true><<<dim3(HH/128, cdiv(M2, 128)), 256, HG_DYNSMEM>>>(
            lrh, lrl, Whidh, Whidl, b_hidden, xcB, xcBh, xcBl, M2, HH, HH, xcA);

        repeat_kernel<<<cdiv(M2*64, 256), 256>>>(hcA, hcAh, hcAl, dA,
                                                 hcB, hcBh, hcBl, dB, M2);

        float* t;  bf16* bt;
        t = xcA; xcA = xcB; xcB = t;
        t = hcA; hcA = hcB; hcB = t;
        t = dA;  dA  = dB;  dB  = t;
        bt = xcAh; xcAh = xcBh; xcBh = bt;
        bt = xcAl; xcAl = xcBl; xcBl = bt;
        bt = hcAh; hcAh = hcBh; hcBh = bt;
        bt = hcAl; hcAl = hcBl; hcBl = bt;
    }

    // ---- leaf step (M = 32768) ----
    {
        int M = MAXM;
        int gy = M / 128;
        hgemm3<0, true, false><<<dim3(768/128, gy), 256, HG_DYNSMEM>>>(
            xcAh, xcAl, Wihh, Wihl, b_ih, gi, nullptr, nullptr, M, 768, HH, nullptr);
        hgemm3<0, true, false><<<dim3(768/128, gy), 256, HG_DYNSMEM>>>(
            hcAh, hcAl, Whhh, Whhl, b_hh, gh, nullptr, nullptr, M, 768, RR, nullptr);
        gru_split_kernel<<<cdiv(M*RR, 256), 256>>>(gi, gh, hcA, hcAh, hcAl, M);
        hb_kernel<<<cdiv(M*32, 256), 256>>>(xcA, hcA, W_hb, b_hb, dA, dA, M);
        out_kernel<<<cdiv(M*(HH+1), 256), 256>>>(xcA, dA, (float*)d_out);
    }
}